// round 6
// baseline (speedup 1.0000x reference)
#include <cuda_runtime.h>
#include <cuda_bf16.h>
#include <cuda_fp16.h>
#include <math.h>
#include <stdint.h>

// ---------------- scratch (static device globals; no allocation) ----------------
__device__ float          g_h1[4096 * 256];
__device__ __nv_bfloat16  g_h2hi[4096 * 512];
__device__ __nv_bfloat16  g_h2lo[4096 * 512];
__device__ __nv_bfloat16  g_W3thi[4096 * 512];   // W3^T hi  [N=4096, K=512]
__device__ __nv_bfloat16  g_W3tlo[4096 * 512];   // W3^T lo
__device__ __half         g_S [4096u * 4096u];   // tanh(h2 @ sW3 + sb3)  fp16
__device__ float          g_f [4096 * 128];
__device__ float          g_FL[4096 * 256];

// ---------------- helpers ----------------
__device__ __forceinline__ uint32_t smem_u32(const void* p) {
    uint32_t a;
    asm("{ .reg .u64 t; cvta.to.shared.u64 t, %1; cvt.u32.u64 %0, t; }" : "=r"(a) : "l"(p));
    return a;
}
__device__ __forceinline__ void cp_async16(uint32_t dst, const void* src) {
    asm volatile("cp.async.cg.shared.global [%0], [%1], 16;" :: "r"(dst), "l"(src));
}
#define CP_COMMIT() asm volatile("cp.async.commit_group;" ::: "memory")

__device__ __forceinline__ void ldsm_x4(uint32_t (&r)[4], uint32_t addr) {
    asm volatile("ldmatrix.sync.aligned.m8n8.x4.shared.b16 {%0,%1,%2,%3}, [%4];"
                 : "=r"(r[0]), "=r"(r[1]), "=r"(r[2]), "=r"(r[3]) : "r"(addr));
}
__device__ __forceinline__ void mma16816(float (&d)[4], const uint32_t (&a)[4],
                                         uint32_t b0, uint32_t b1) {
    asm volatile(
        "mma.sync.aligned.m16n8k16.row.col.f32.bf16.bf16.f32 "
        "{%0,%1,%2,%3}, {%4,%5,%6,%7}, {%8,%9}, {%0,%1,%2,%3};"
        : "+f"(d[0]), "+f"(d[1]), "+f"(d[2]), "+f"(d[3])
        : "r"(a[0]), "r"(a[1]), "r"(a[2]), "r"(a[3]), "r"(b0), "r"(b1));
}

// ---------------- 64x64-tile fp32 SIMT GEMM + bias + activation ----------------
template <int ACT>  // 0 = relu, 1 = tanh
__global__ __launch_bounds__(256) void gemm64_act(
    const float* __restrict__ A, const float* __restrict__ W,
    const float* __restrict__ bias, float* __restrict__ C,
    int M, int N, int K)
{
    constexpr int BK = 16;
    __shared__ float As[BK][64 + 4];
    __shared__ float Bs[BK][64];

    const int tid = threadIdx.x;
    const int tx  = tid & 15;
    const int ty  = tid >> 4;
    const int bm  = blockIdx.y;
    const int bn  = blockIdx.x;

    const float* Ab = A + (size_t)bm * 64 * K;
    const float* Wb = W + (size_t)bn * 64;

    float acc[4][4];
    #pragma unroll
    for (int i = 0; i < 4; i++)
        #pragma unroll
        for (int j = 0; j < 4; j++) acc[i][j] = 0.0f;

    for (int k0 = 0; k0 < K; k0 += BK) {
        {
            int row = tid >> 2;
            int c4  = (tid & 3) * 4;
            float4 v = *reinterpret_cast<const float4*>(Ab + (size_t)row * K + k0 + c4);
            As[c4 + 0][row] = v.x; As[c4 + 1][row] = v.y;
            As[c4 + 2][row] = v.z; As[c4 + 3][row] = v.w;
        }
        {
            int row = tid >> 4;
            int c4  = (tid & 15) * 4;
            *reinterpret_cast<float4*>(&Bs[row][c4]) =
                *reinterpret_cast<const float4*>(Wb + (size_t)(k0 + row) * N + c4);
        }
        __syncthreads();
        #pragma unroll
        for (int k = 0; k < BK; k++) {
            float a[4], b[4];
            #pragma unroll
            for (int i = 0; i < 4; i++) a[i] = As[k][ty * 4 + i];
            #pragma unroll
            for (int j = 0; j < 4; j++) b[j] = Bs[k][tx * 4 + j];
            #pragma unroll
            for (int i = 0; i < 4; i++)
                #pragma unroll
                for (int j = 0; j < 4; j++) acc[i][j] = fmaf(a[i], b[j], acc[i][j]);
        }
        __syncthreads();
    }

    #pragma unroll
    for (int i = 0; i < 4; i++) {
        int m = bm * 64 + ty * 4 + i;
        int n = bn * 64 + tx * 4;
        float4 v; float* vv = &v.x;
        #pragma unroll
        for (int t = 0; t < 4; t++) {
            float x = acc[i][t] + bias[n + t];
            if (ACT == 0) x = fmaxf(x, 0.0f); else x = tanhf(x);
            vv[t] = x;
        }
        *reinterpret_cast<float4*>(C + (size_t)m * N + n) = v;
    }
}

// 64x64-tile GEMM, relu epilogue emitting bf16 hi/lo split
__global__ __launch_bounds__(256) void gemm64_relu_split(
    const float* __restrict__ A, const float* __restrict__ W,
    const float* __restrict__ bias,
    __nv_bfloat16* __restrict__ Chi, __nv_bfloat16* __restrict__ Clo,
    int M, int N, int K)
{
    constexpr int BK = 16;
    __shared__ float As[BK][64 + 4];
    __shared__ float Bs[BK][64];

    const int tid = threadIdx.x;
    const int tx  = tid & 15;
    const int ty  = tid >> 4;
    const int bm  = blockIdx.y;
    const int bn  = blockIdx.x;

    const float* Ab = A + (size_t)bm * 64 * K;
    const float* Wb = W + (size_t)bn * 64;

    float acc[4][4];
    #pragma unroll
    for (int i = 0; i < 4; i++)
        #pragma unroll
        for (int j = 0; j < 4; j++) acc[i][j] = 0.0f;

    for (int k0 = 0; k0 < K; k0 += BK) {
        {
            int row = tid >> 2;
            int c4  = (tid & 3) * 4;
            float4 v = *reinterpret_cast<const float4*>(Ab + (size_t)row * K + k0 + c4);
            As[c4 + 0][row] = v.x; As[c4 + 1][row] = v.y;
            As[c4 + 2][row] = v.z; As[c4 + 3][row] = v.w;
        }
        {
            int row = tid >> 4;
            int c4  = (tid & 15) * 4;
            *reinterpret_cast<float4*>(&Bs[row][c4]) =
                *reinterpret_cast<const float4*>(Wb + (size_t)(k0 + row) * N + c4);
        }
        __syncthreads();
        #pragma unroll
        for (int k = 0; k < BK; k++) {
            float a[4], b[4];
            #pragma unroll
            for (int i = 0; i < 4; i++) a[i] = As[k][ty * 4 + i];
            #pragma unroll
            for (int j = 0; j < 4; j++) b[j] = Bs[k][tx * 4 + j];
            #pragma unroll
            for (int i = 0; i < 4; i++)
                #pragma unroll
                for (int j = 0; j < 4; j++) acc[i][j] = fmaf(a[i], b[j], acc[i][j]);
        }
        __syncthreads();
    }

    #pragma unroll
    for (int i = 0; i < 4; i++) {
        int m = bm * 64 + ty * 4 + i;
        int n = bn * 64 + tx * 4;
        __nv_bfloat16 hv[4], lv[4];
        #pragma unroll
        for (int t = 0; t < 4; t++) {
            float x = fmaxf(acc[i][t] + bias[n + t], 0.0f);
            hv[t] = __float2bfloat16(x);
            lv[t] = __float2bfloat16(x - __bfloat162float(hv[t]));
        }
        *reinterpret_cast<uint2*>(Chi + (size_t)m * N + n) = *reinterpret_cast<uint2*>(hv);
        *reinterpret_cast<uint2*>(Clo + (size_t)m * N + n) = *reinterpret_cast<uint2*>(lv);
    }
}

// W3 [K=512, N=4096] f32 -> W3^T hi/lo [4096, 512] bf16
__global__ __launch_bounds__(256) void transpose_split(
    const float* __restrict__ W, __nv_bfloat16* __restrict__ Thi,
    __nv_bfloat16* __restrict__ Tlo, int K, int N)
{
    __shared__ float t[32][33];
    int tx = threadIdx.x, ty = threadIdx.y;       // 32 x 8
    int bx = blockIdx.x, by = blockIdx.y;
    #pragma unroll
    for (int i = 0; i < 4; i++) {
        int row = by * 32 + ty + i * 8;
        int col = bx * 32 + tx;
        t[ty + i * 8][tx] = W[(size_t)row * N + col];
    }
    __syncthreads();
    #pragma unroll
    for (int i = 0; i < 4; i++) {
        int n = bx * 32 + ty + i * 8;
        int k = by * 32 + tx;
        float v = t[tx][ty + i * 8];
        __nv_bfloat16 hi = __float2bfloat16(v);
        __nv_bfloat16 lo = __float2bfloat16(v - __bfloat162float(hi));
        Thi[(size_t)n * K + k] = hi;
        Tlo[(size_t)n * K + k] = lo;
    }
}

// ---------------- GEMM3 via mma.sync (bf16 3-split, fp32 accum) ----------------
// CTA 128x128, 8 warps (4m x 2n, warp tile 32x64). K in 8 chunks of 64.
// 3-stage cp.async ring; register double-buffered fragments (prefetch kk+1 /
// next-chunk kk=0 while issuing current 48 MMAs). Correct ordering:
// wait_group -> __syncthreads -> smem reads.
__global__ __launch_bounds__(256, 1) void gemm3_mma(
    const __nv_bfloat16* __restrict__ Ahi, const __nv_bfloat16* __restrict__ Alo,
    const __nv_bfloat16* __restrict__ Bhi, const __nv_bfloat16* __restrict__ Blo,
    const float* __restrict__ bias, __half* __restrict__ S)
{
    extern __shared__ char dynsmem[];
    const uint32_t sbase = smem_u32(dynsmem);    // 3 stages x 64 KB

    const int tid  = threadIdx.x;
    const int lane = tid & 31;
    const int wid  = tid >> 5;
    const int wm   = wid & 3;
    const int wn   = wid >> 2;
    const int tile_n = blockIdx.x, tile_m = blockIdx.y;

    auto load_chunk = [&](int stage, int kc) {
        const uint32_t st = sbase + stage * 65536;
        #pragma unroll
        for (int it = 0; it < 16; it++) {
            int u   = tid + it * 256;
            int buf = u >> 10;
            int idx = u & 1023;
            int row = idx >> 3;
            int c   = idx & 7;
            uint32_t dst = st + buf * 16384 + row * 128 + ((c ^ (row & 7)) << 4);
            const __nv_bfloat16* src;
            int grow;
            if (buf < 2) { grow = tile_m * 128 + row; src = (buf == 0) ? Ahi : Alo; }
            else         { grow = tile_n * 128 + row; src = (buf == 2) ? Bhi : Blo; }
            cp_async16(dst, (const char*)src + ((size_t)grow * 512 + kc * 64 + c * 8) * 2);
        }
        CP_COMMIT();
    };

    float acc[2][8][4];
    #pragma unroll
    for (int i = 0; i < 2; i++)
        #pragma unroll
        for (int j = 0; j < 8; j++)
            #pragma unroll
            for (int t = 0; t < 4; t++) acc[i][j][t] = 0.0f;

    // fragment double buffers
    uint32_t ah[2][2][4], al[2][2][4], bh[2][4][4], bl[2][4][4];

    const int a_row_in = (lane & 15);
    const int a_cb_add = (lane >> 4);
    const int b_row_in = ((lane >> 4) << 3) + (lane & 7);
    const int b_cb_add = (lane >> 3) & 1;

    load_chunk(0, 0);
    load_chunk(1, 1);

    // prologue: chunk 0 visible, prefetch its kk=0 fragments
    asm volatile("cp.async.wait_group 1;" ::: "memory");
    __syncthreads();

    #define LOAD_FRAGS(BUF, ST, CB) do {                                         \
        uint32_t _st = (ST);                                                     \
        int _cb = (CB);                                                          \
        _Pragma("unroll")                                                        \
        for (int mi = 0; mi < 2; mi++) {                                         \
            int row = wm * 32 + mi * 16 + a_row_in;                              \
            uint32_t off = row * 128 + (((_cb + a_cb_add) ^ (row & 7)) << 4);    \
            ldsm_x4(ah[BUF][mi], _st + off);                                     \
            ldsm_x4(al[BUF][mi], _st + 16384 + off);                             \
        }                                                                        \
        _Pragma("unroll")                                                        \
        for (int nq = 0; nq < 4; nq++) {                                         \
            int row = wn * 64 + nq * 16 + b_row_in;                              \
            uint32_t off = row * 128 + (((_cb + b_cb_add) ^ (row & 7)) << 4);    \
            ldsm_x4(bh[BUF][nq], _st + 32768 + off);                             \
            ldsm_x4(bl[BUF][nq], _st + 49152 + off);                             \
        }                                                                        \
    } while (0)

    #define DO_MMAS(BUF) do {                                                    \
        _Pragma("unroll")                                                        \
        for (int nq = 0; nq < 4; nq++) {                                         \
            _Pragma("unroll")                                                    \
            for (int mi = 0; mi < 2; mi++) {                                     \
                mma16816(acc[mi][2*nq],   ah[BUF][mi], bh[BUF][nq][0], bh[BUF][nq][1]); \
                mma16816(acc[mi][2*nq],   ah[BUF][mi], bl[BUF][nq][0], bl[BUF][nq][1]); \
                mma16816(acc[mi][2*nq],   al[BUF][mi], bh[BUF][nq][0], bh[BUF][nq][1]); \
                mma16816(acc[mi][2*nq+1], ah[BUF][mi], bh[BUF][nq][2], bh[BUF][nq][3]); \
                mma16816(acc[mi][2*nq+1], ah[BUF][mi], bl[BUF][nq][2], bl[BUF][nq][3]); \
                mma16816(acc[mi][2*nq+1], al[BUF][mi], bh[BUF][nq][2], bh[BUF][nq][3]); \
            }                                                                    \
        }                                                                        \
    } while (0)

    LOAD_FRAGS(0, sbase, 0);

    for (int c = 0; c < 8; ++c) {
        const uint32_t st = sbase + (c % 3) * 65536;
        #pragma unroll
        for (int kk = 0; kk < 4; ++kk) {
            if (kk == 0) {
                if (kk < 3) LOAD_FRAGS(1, st, (kk + 1) * 2);
                DO_MMAS(0);
            } else if (kk == 1) {
                LOAD_FRAGS(0, st, (kk + 1) * 2);
                DO_MMAS(1);
            } else if (kk == 2) {
                LOAD_FRAGS(1, st, (kk + 1) * 2);
                DO_MMAS(0);
            } else {
                if (c < 7) {
                    // next chunk's data must be visible to ALL threads
                    asm volatile("cp.async.wait_group 0;" ::: "memory");
                    __syncthreads();                       // also retires chunk-c reads
                    if (c + 2 < 8) load_chunk((c + 2) % 3, c + 2);
                    LOAD_FRAGS(0, sbase + ((c + 1) % 3) * 65536, 0);
                }
                DO_MMAS(1);
            }
        }
    }
    #undef LOAD_FRAGS
    #undef DO_MMAS

    // epilogue: bias + tanh -> fp16, 2 cols per store (uint32)
    const int col0 = tile_n * 128 + wn * 64 + (lane & 3) * 2;
    #pragma unroll
    for (int mi = 0; mi < 2; mi++) {
        int r0 = tile_m * 128 + wm * 32 + mi * 16 + (lane >> 2);
        #pragma unroll
        for (int nb = 0; nb < 8; nb++) {
            int col = col0 + nb * 8;
            float b0 = __ldg(bias + col), b1 = __ldg(bias + col + 1);
            __half2 h0 = __floats2half2_rn(tanhf(acc[mi][nb][0] + b0),
                                           tanhf(acc[mi][nb][1] + b1));
            __half2 h1 = __floats2half2_rn(tanhf(acc[mi][nb][2] + b0),
                                           tanhf(acc[mi][nb][3] + b1));
            *reinterpret_cast<__half2*>(S + (size_t)r0 * 4096 + col) = h0;
            *reinterpret_cast<__half2*>(S + (size_t)(r0 + 8) * 4096 + col) = h1;
        }
    }
}

// ---------------- assemble one channel + separable 5x5 Gaussian ----------------
__global__ __launch_bounds__(256) void assemble_conv(
    const __half* __restrict__ S, const float* __restrict__ FL,
    const float* __restrict__ msg, float* __restrict__ out)
{
    __shared__ float img[64 * 64];
    __shared__ float tmp[64 * 64];
    __shared__ float fl[256];

    const int b   = blockIdx.x;
    const int ch  = blockIdx.y;
    const int tid = threadIdx.x;

    float g[5];
    {
        float s = 0.0f;
        #pragma unroll
        for (int i = 0; i < 5; i++) {
            float c = (float)(i - 2);
            g[i] = expf(-c * c * 0.5f);
            s += g[i];
        }
        #pragma unroll
        for (int i = 0; i < 5; i++) g[i] /= s;
    }

    if (ch == 0) {
        const __half2* S2 = reinterpret_cast<const __half2*>(S + (size_t)b * 4096);
        #pragma unroll
        for (int it = 0; it < 8; it++) {
            int i2 = tid + it * 256;               // 0..2047
            float2 f = __half22float2(S2[i2]);
            img[2 * i2]     = f.x;
            img[2 * i2 + 1] = f.y;
        }
    } else if (ch == 1) {
        fl[tid] = FL[(size_t)b * 256 + tid];
        __syncthreads();
        #pragma unroll
        for (int it = 0; it < 16; it++) {
            int idx = tid + it * 256;
            int p = idx >> 6, q = idx & 63;
            float pp = (float)(p * 15) / 63.0f;
            float pq = (float)(q * 15) / 63.0f;
            int lp = (int)pp, lq = (int)pq;
            float wp = pp - (float)lp, wq = pq - (float)lq;
            int hp = min(lp + 1, 15), hq = min(lq + 1, 15);
            float v00 = fl[lp * 16 + lq], v01 = fl[lp * 16 + hq];
            float v10 = fl[hp * 16 + lq], v11 = fl[hp * 16 + hq];
            float top = (1.0f - wq) * v00 + wq * v01;
            float bot = (1.0f - wq) * v10 + wq * v11;
            img[idx] = (1.0f - wp) * top + wp * bot;
        }
    } else {
        if (tid < 64) fl[tid] = msg[(size_t)b * 64 + tid];
        __syncthreads();
        #pragma unroll
        for (int it = 0; it < 16; it++) {
            int idx = tid + it * 256;
            int p = idx >> 6, q = idx & 63;
            img[idx] = fl[((p >> 3) << 3) + (q >> 3)];
        }
    }
    __syncthreads();

    #pragma unroll
    for (int it = 0; it < 16; it++) {
        int idx = tid + it * 256;
        int p = idx >> 6, q = idx & 63;
        float s = 0.0f;
        #pragma unroll
        for (int d = -2; d <= 2; d++) {
            int qq = q + d;
            if (qq >= 0 && qq < 64) s = fmaf(g[d + 2], img[(p << 6) + qq], s);
        }
        tmp[idx] = s;
    }
    __syncthreads();

    float* outc = out + ((size_t)b * 3 + ch) * 4096;
    #pragma unroll
    for (int it = 0; it < 4; it++) {
        int i4 = tid + it * 256;
        int p  = i4 >> 4;
        int q0 = (i4 & 15) << 2;
        float4 s = make_float4(0.f, 0.f, 0.f, 0.f);
        #pragma unroll
        for (int d = -2; d <= 2; d++) {
            int pp = p + d;
            if (pp >= 0 && pp < 64) {
                float4 t4 = *reinterpret_cast<float4*>(&tmp[(pp << 6) + q0]);
                float w = g[d + 2];
                s.x = fmaf(w, t4.x, s.x);
                s.y = fmaf(w, t4.y, s.y);
                s.z = fmaf(w, t4.z, s.z);
                s.w = fmaf(w, t4.w, s.w);
            }
        }
        *reinterpret_cast<float4*>(outc + (p << 6) + q0) = s;
    }
}

// ---------------- launch ----------------
extern "C" void kernel_launch(void* const* d_in, const int* in_sizes, int n_in,
                              void* d_out, int out_size)
{
    const float* msg = (const float*)d_in[0];
    const float* sW1 = (const float*)d_in[1];
    const float* sb1 = (const float*)d_in[2];
    const float* sW2 = (const float*)d_in[3];
    const float* sb2 = (const float*)d_in[4];
    const float* sW3 = (const float*)d_in[5];
    const float* sb3 = (const float*)d_in[6];
    const float* fW1 = (const float*)d_in[7];
    const float* fb1 = (const float*)d_in[8];
    const float* fW2 = (const float*)d_in[9];
    const float* fb2 = (const float*)d_in[10];
    float* out = (float*)d_out;

    float *h1, *f, *FL;
    __half* S;
    __nv_bfloat16 *h2hi, *h2lo, *w3hi, *w3lo;
    cudaGetSymbolAddress((void**)&h1,   g_h1);
    cudaGetSymbolAddress((void**)&h2hi, g_h2hi);
    cudaGetSymbolAddress((void**)&h2lo, g_h2lo);
    cudaGetSymbolAddress((void**)&w3hi, g_W3thi);
    cudaGetSymbolAddress((void**)&w3lo, g_W3tlo);
    cudaGetSymbolAddress((void**)&S,    g_S);
    cudaGetSymbolAddress((void**)&f,    g_f);
    cudaGetSymbolAddress((void**)&FL,   g_FL);

    cudaFuncSetAttribute(gemm3_mma, cudaFuncAttributeMaxDynamicSharedMemorySize, 196608);

    dim3 blk(256);
    // spatial chain
    gemm64_act<0><<<dim3(4, 64), blk>>>(msg, sW1, sb1, h1, 4096, 256, 64);
    gemm64_relu_split<<<dim3(8, 64), blk>>>(h1, sW2, sb2, h2hi, h2lo, 4096, 512, 256);
    transpose_split<<<dim3(4096 / 32, 512 / 32), dim3(32, 8)>>>(sW3, w3hi, w3lo, 512, 4096);
    gemm3_mma<<<dim3(32, 32), 256, 196608>>>(h2hi, h2lo, w3hi, w3lo, sb3, S);
    // freq chain
    gemm64_act<0><<<dim3(2, 64), blk>>>(msg, fW1, fb1, f, 4096, 128, 64);
    gemm64_act<1><<<dim3(4, 64), blk>>>(f, fW2, fb2, FL, 4096, 256, 128);
    // assemble + depthwise Gaussian (one channel per CTA)
    assemble_conv<<<dim3(4096, 3), 256>>>(S, FL, msg, out);
}

// round 8
// speedup vs baseline: 1.4135x; 1.4135x over previous
#include <cuda_runtime.h>
#include <cuda_fp16.h>
#include <math.h>
#include <stdint.h>

// ---------------- scratch (static device globals; no allocation) ----------------
__device__ float   g_h1[4096 * 256];
__device__ __half  g_h2 [4096 * 512];     // relu(h1 @ sW2 + sb2), fp16
__device__ __half  g_W3t[4096 * 512];     // W3^T fp16  [N=4096, K=512]
__device__ __half  g_S  [4096u * 4096u];  // tanh(h2 @ sW3 + sb3), fp16
__device__ float   g_f  [4096 * 128];
__device__ float   g_FL [4096 * 256];

// ---------------- helpers ----------------
__device__ __forceinline__ uint32_t smem_u32(const void* p) {
    uint32_t a;
    asm("{ .reg .u64 t; cvta.to.shared.u64 t, %1; cvt.u32.u64 %0, t; }" : "=r"(a) : "l"(p));
    return a;
}
__device__ __forceinline__ void cp_async16(uint32_t dst, const void* src) {
    asm volatile("cp.async.cg.shared.global [%0], [%1], 16;" :: "r"(dst), "l"(src));
}
#define CP_COMMIT() asm volatile("cp.async.commit_group;" ::: "memory")

__device__ __forceinline__ void ldsm_x4(uint32_t (&r)[4], uint32_t addr) {
    asm volatile("ldmatrix.sync.aligned.m8n8.x4.shared.b16 {%0,%1,%2,%3}, [%4];"
                 : "=r"(r[0]), "=r"(r[1]), "=r"(r[2]), "=r"(r[3]) : "r"(addr));
}
__device__ __forceinline__ void mma16816h(float (&d)[4], const uint32_t (&a)[4],
                                          uint32_t b0, uint32_t b1) {
    asm volatile(
        "mma.sync.aligned.m16n8k16.row.col.f32.f16.f16.f32 "
        "{%0,%1,%2,%3}, {%4,%5,%6,%7}, {%8,%9}, {%0,%1,%2,%3};"
        : "+f"(d[0]), "+f"(d[1]), "+f"(d[2]), "+f"(d[3])
        : "r"(a[0]), "r"(a[1]), "r"(a[2]), "r"(a[3]), "r"(b0), "r"(b1));
}

// ---------------- 64x64-tile fp32 SIMT GEMM + bias + activation ----------------
template <int ACT>  // 0 = relu, 1 = tanh
__global__ __launch_bounds__(256) void gemm64_act(
    const float* __restrict__ A, const float* __restrict__ W,
    const float* __restrict__ bias, float* __restrict__ C,
    int M, int N, int K)
{
    constexpr int BK = 16;
    __shared__ float As[BK][64 + 4];
    __shared__ float Bs[BK][64];

    const int tid = threadIdx.x;
    const int tx  = tid & 15;
    const int ty  = tid >> 4;
    const int bm  = blockIdx.y;
    const int bn  = blockIdx.x;

    const float* Ab = A + (size_t)bm * 64 * K;
    const float* Wb = W + (size_t)bn * 64;

    float acc[4][4];
    #pragma unroll
    for (int i = 0; i < 4; i++)
        #pragma unroll
        for (int j = 0; j < 4; j++) acc[i][j] = 0.0f;

    for (int k0 = 0; k0 < K; k0 += BK) {
        {
            int row = tid >> 2;
            int c4  = (tid & 3) * 4;
            float4 v = *reinterpret_cast<const float4*>(Ab + (size_t)row * K + k0 + c4);
            As[c4 + 0][row] = v.x; As[c4 + 1][row] = v.y;
            As[c4 + 2][row] = v.z; As[c4 + 3][row] = v.w;
        }
        {
            int row = tid >> 4;
            int c4  = (tid & 15) * 4;
            *reinterpret_cast<float4*>(&Bs[row][c4]) =
                *reinterpret_cast<const float4*>(Wb + (size_t)(k0 + row) * N + c4);
        }
        __syncthreads();
        #pragma unroll
        for (int k = 0; k < BK; k++) {
            float a[4], b[4];
            #pragma unroll
            for (int i = 0; i < 4; i++) a[i] = As[k][ty * 4 + i];
            #pragma unroll
            for (int j = 0; j < 4; j++) b[j] = Bs[k][tx * 4 + j];
            #pragma unroll
            for (int i = 0; i < 4; i++)
                #pragma unroll
                for (int j = 0; j < 4; j++) acc[i][j] = fmaf(a[i], b[j], acc[i][j]);
        }
        __syncthreads();
    }

    #pragma unroll
    for (int i = 0; i < 4; i++) {
        int m = bm * 64 + ty * 4 + i;
        int n = bn * 64 + tx * 4;
        float4 v; float* vv = &v.x;
        #pragma unroll
        for (int t = 0; t < 4; t++) {
            float x = acc[i][t] + bias[n + t];
            if (ACT == 0) x = fmaxf(x, 0.0f); else x = tanhf(x);
            vv[t] = x;
        }
        *reinterpret_cast<float4*>(C + (size_t)m * N + n) = v;
    }
}

// 64x64-tile GEMM, relu epilogue -> fp16 (feeds tensor GEMM3)
__global__ __launch_bounds__(256) void gemm64_relu_h16(
    const float* __restrict__ A, const float* __restrict__ W,
    const float* __restrict__ bias, __half* __restrict__ C,
    int M, int N, int K)
{
    constexpr int BK = 16;
    __shared__ float As[BK][64 + 4];
    __shared__ float Bs[BK][64];

    const int tid = threadIdx.x;
    const int tx  = tid & 15;
    const int ty  = tid >> 4;
    const int bm  = blockIdx.y;
    const int bn  = blockIdx.x;

    const float* Ab = A + (size_t)bm * 64 * K;
    const float* Wb = W + (size_t)bn * 64;

    float acc[4][4];
    #pragma unroll
    for (int i = 0; i < 4; i++)
        #pragma unroll
        for (int j = 0; j < 4; j++) acc[i][j] = 0.0f;

    for (int k0 = 0; k0 < K; k0 += BK) {
        {
            int row = tid >> 2;
            int c4  = (tid & 3) * 4;
            float4 v = *reinterpret_cast<const float4*>(Ab + (size_t)row * K + k0 + c4);
            As[c4 + 0][row] = v.x; As[c4 + 1][row] = v.y;
            As[c4 + 2][row] = v.z; As[c4 + 3][row] = v.w;
        }
        {
            int row = tid >> 4;
            int c4  = (tid & 15) * 4;
            *reinterpret_cast<float4*>(&Bs[row][c4]) =
                *reinterpret_cast<const float4*>(Wb + (size_t)(k0 + row) * N + c4);
        }
        __syncthreads();
        #pragma unroll
        for (int k = 0; k < BK; k++) {
            float a[4], b[4];
            #pragma unroll
            for (int i = 0; i < 4; i++) a[i] = As[k][ty * 4 + i];
            #pragma unroll
            for (int j = 0; j < 4; j++) b[j] = Bs[k][tx * 4 + j];
            #pragma unroll
            for (int i = 0; i < 4; i++)
                #pragma unroll
                for (int j = 0; j < 4; j++) acc[i][j] = fmaf(a[i], b[j], acc[i][j]);
        }
        __syncthreads();
    }

    #pragma unroll
    for (int i = 0; i < 4; i++) {
        int m = bm * 64 + ty * 4 + i;
        int n = bn * 64 + tx * 4;
        __half2 h0 = __floats2half2_rn(fmaxf(acc[i][0] + bias[n + 0], 0.0f),
                                       fmaxf(acc[i][1] + bias[n + 1], 0.0f));
        __half2 h1 = __floats2half2_rn(fmaxf(acc[i][2] + bias[n + 2], 0.0f),
                                       fmaxf(acc[i][3] + bias[n + 3], 0.0f));
        *reinterpret_cast<__half2*>(C + (size_t)m * N + n)     = h0;
        *reinterpret_cast<__half2*>(C + (size_t)m * N + n + 2) = h1;
    }
}

// W3 [K=512, N=4096] f32 -> W3^T fp16 [4096, 512]
__global__ __launch_bounds__(256) void transpose_h16(
    const float* __restrict__ W, __half* __restrict__ T, int K, int N)
{
    __shared__ float t[32][33];
    int tx = threadIdx.x, ty = threadIdx.y;       // 32 x 8
    int bx = blockIdx.x, by = blockIdx.y;
    #pragma unroll
    for (int i = 0; i < 4; i++) {
        int row = by * 32 + ty + i * 8;
        int col = bx * 32 + tx;
        t[ty + i * 8][tx] = W[(size_t)row * N + col];
    }
    __syncthreads();
    #pragma unroll
    for (int i = 0; i < 4; i++) {
        int n = bx * 32 + ty + i * 8;
        int k = by * 32 + tx;
        T[(size_t)n * K + k] = __float2half_rn(t[tx][ty + i * 8]);
    }
}

// ---------------- GEMM3 via mma.sync fp16 (single pass, fp32 accum) ----------------
// S[4096,4096] = tanh(h2 @ W3 + b3). CTA 128x128, 8 warps (4m x 2n, warp 32x64).
// K in 8 chunks of 64. Stage = A(128x128B) + B(128x128B) = 32 KB; 3 stages = 96 KB
// -> 2 CTAs/SM. One barrier per chunk; order: wait_group -> barrier -> reads.
__global__ __launch_bounds__(256, 2) void gemm3_mma(
    const __half* __restrict__ A, const __half* __restrict__ B,
    const float* __restrict__ bias, __half* __restrict__ S)
{
    extern __shared__ char dynsmem[];
    const uint32_t sbase = smem_u32(dynsmem);    // 3 stages x 32 KB

    const int tid  = threadIdx.x;
    const int lane = tid & 31;
    const int wid  = tid >> 5;
    const int wm   = wid & 3;
    const int wn   = wid >> 2;
    const int tile_n = blockIdx.x, tile_m = blockIdx.y;

    auto load_chunk = [&](int stage, int kc) {
        const uint32_t st = sbase + stage * 32768;
        #pragma unroll
        for (int it = 0; it < 8; it++) {
            int u   = tid + it * 256;
            int buf = u >> 10;                 // 0 = A, 1 = B
            int idx = u & 1023;
            int row = idx >> 3;
            int c   = idx & 7;
            uint32_t dst = st + buf * 16384 + row * 128 + ((c ^ (row & 7)) << 4);
            const __half* src = buf ? B : A;
            int grow = (buf ? tile_n : tile_m) * 128 + row;
            cp_async16(dst, (const char*)src + ((size_t)grow * 512 + kc * 64 + c * 8) * 2);
        }
        CP_COMMIT();
    };

    float acc[2][8][4];
    #pragma unroll
    for (int i = 0; i < 2; i++)
        #pragma unroll
        for (int j = 0; j < 8; j++)
            #pragma unroll
            for (int t = 0; t < 4; t++) acc[i][j][t] = 0.0f;

    load_chunk(0, 0);
    load_chunk(1, 1);

    // ldmatrix lane mapping (validated R3):
    const int a_row_in = (lane & 15);
    const int a_cb_add = (lane >> 4);
    const int b_row_in = ((lane >> 4) << 3) + (lane & 7);
    const int b_cb_add = (lane >> 3) & 1;

    for (int c = 0; c < 8; ++c) {
        if (c < 7) asm volatile("cp.async.wait_group 1;" ::: "memory");
        else       asm volatile("cp.async.wait_group 0;" ::: "memory");
        __syncthreads();                        // chunk c visible; chunk c-1 reads retired
        if (c + 2 < 8) load_chunk((c + 2) % 3, c + 2);

        const uint32_t aB = sbase + (c % 3) * 32768;
        const uint32_t bB = aB + 16384;

        #pragma unroll
        for (int kk = 0; kk < 4; kk++) {        // four k16 steps per 64-chunk
            const int cb = kk * 2;
            uint32_t ah[2][4];
            #pragma unroll
            for (int mi = 0; mi < 2; mi++) {
                int row = wm * 32 + mi * 16 + a_row_in;
                uint32_t off = row * 128 + (((cb + a_cb_add) ^ (row & 7)) << 4);
                ldsm_x4(ah[mi], aB + off);
            }
            #pragma unroll
            for (int nq = 0; nq < 4; nq++) {
                int row = wn * 64 + nq * 16 + b_row_in;
                uint32_t off = row * 128 + (((cb + b_cb_add) ^ (row & 7)) << 4);
                uint32_t bh[4];
                ldsm_x4(bh, bB + off);
                #pragma unroll
                for (int mi = 0; mi < 2; mi++) {
                    mma16816h(acc[mi][2 * nq],     ah[mi], bh[0], bh[1]);
                    mma16816h(acc[mi][2 * nq + 1], ah[mi], bh[2], bh[3]);
                }
            }
        }
    }

    // epilogue: bias + tanh -> fp16
    const int col0 = tile_n * 128 + wn * 64 + (lane & 3) * 2;
    #pragma unroll
    for (int mi = 0; mi < 2; mi++) {
        int r0 = tile_m * 128 + wm * 32 + mi * 16 + (lane >> 2);
        #pragma unroll
        for (int nb = 0; nb < 8; nb++) {
            int col = col0 + nb * 8;
            float b0 = __ldg(bias + col), b1 = __ldg(bias + col + 1);
            __half2 h0 = __floats2half2_rn(tanhf(acc[mi][nb][0] + b0),
                                           tanhf(acc[mi][nb][1] + b1));
            __half2 h1 = __floats2half2_rn(tanhf(acc[mi][nb][2] + b0),
                                           tanhf(acc[mi][nb][3] + b1));
            *reinterpret_cast<__half2*>(S + (size_t)r0 * 4096 + col) = h0;
            *reinterpret_cast<__half2*>(S + (size_t)(r0 + 8) * 4096 + col) = h1;
        }
    }
}

// ---------------- assemble one channel + separable 5x5 Gaussian ----------------
__global__ __launch_bounds__(256) void assemble_conv(
    const __half* __restrict__ S, const float* __restrict__ FL,
    const float* __restrict__ msg, float* __restrict__ out)
{
    __shared__ float img[64 * 64];
    __shared__ float tmp[64 * 64];
    __shared__ float fl[256];

    const int b   = blockIdx.x;
    const int ch  = blockIdx.y;
    const int tid = threadIdx.x;

    float g[5];
    {
        float s = 0.0f;
        #pragma unroll
        for (int i = 0; i < 5; i++) {
            float c = (float)(i - 2);
            g[i] = expf(-c * c * 0.5f);
            s += g[i];
        }
        #pragma unroll
        for (int i = 0; i < 5; i++) g[i] /= s;
    }

    if (ch == 0) {
        const __half2* S2 = reinterpret_cast<const __half2*>(S + (size_t)b * 4096);
        #pragma unroll
        for (int it = 0; it < 8; it++) {
            int i2 = tid + it * 256;
            float2 f = __half22float2(S2[i2]);
            img[2 * i2]     = f.x;
            img[2 * i2 + 1] = f.y;
        }
    } else if (ch == 1) {
        fl[tid] = FL[(size_t)b * 256 + tid];
        __syncthreads();
        #pragma unroll
        for (int it = 0; it < 16; it++) {
            int idx = tid + it * 256;
            int p = idx >> 6, q = idx & 63;
            float pp = (float)(p * 15) / 63.0f;
            float pq = (float)(q * 15) / 63.0f;
            int lp = (int)pp, lq = (int)pq;
            float wp = pp - (float)lp, wq = pq - (float)lq;
            int hp = min(lp + 1, 15), hq = min(lq + 1, 15);
            float v00 = fl[lp * 16 + lq], v01 = fl[lp * 16 + hq];
            float v10 = fl[hp * 16 + lq], v11 = fl[hp * 16 + hq];
            float top = (1.0f - wq) * v00 + wq * v01;
            float bot = (1.0f - wq) * v10 + wq * v11;
            img[idx] = (1.0f - wp) * top + wp * bot;
        }
    } else {
        if (tid < 64) fl[tid] = msg[(size_t)b * 64 + tid];
        __syncthreads();
        #pragma unroll
        for (int it = 0; it < 16; it++) {
            int idx = tid + it * 256;
            int p = idx >> 6, q = idx & 63;
            img[idx] = fl[((p >> 3) << 3) + (q >> 3)];
        }
    }
    __syncthreads();

    #pragma unroll
    for (int it = 0; it < 16; it++) {
        int idx = tid + it * 256;
        int p = idx >> 6, q = idx & 63;
        float s = 0.0f;
        #pragma unroll
        for (int d = -2; d <= 2; d++) {
            int qq = q + d;
            if (qq >= 0 && qq < 64) s = fmaf(g[d + 2], img[(p << 6) + qq], s);
        }
        tmp[idx] = s;
    }
    __syncthreads();

    float* outc = out + ((size_t)b * 3 + ch) * 4096;
    #pragma unroll
    for (int it = 0; it < 4; it++) {
        int i4 = tid + it * 256;
        int p  = i4 >> 4;
        int q0 = (i4 & 15) << 2;
        float4 s = make_float4(0.f, 0.f, 0.f, 0.f);
        #pragma unroll
        for (int d = -2; d <= 2; d++) {
            int pp = p + d;
            if (pp >= 0 && pp < 64) {
                float4 t4 = *reinterpret_cast<float4*>(&tmp[(pp << 6) + q0]);
                float w = g[d + 2];
                s.x = fmaf(w, t4.x, s.x);
                s.y = fmaf(w, t4.y, s.y);
                s.z = fmaf(w, t4.z, s.z);
                s.w = fmaf(w, t4.w, s.w);
            }
        }
        *reinterpret_cast<float4*>(outc + (p << 6) + q0) = s;
    }
}

// ---------------- launch ----------------
extern "C" void kernel_launch(void* const* d_in, const int* in_sizes, int n_in,
                              void* d_out, int out_size)
{
    const float* msg = (const float*)d_in[0];
    const float* sW1 = (const float*)d_in[1];
    const float* sb1 = (const float*)d_in[2];
    const float* sW2 = (const float*)d_in[3];
    const float* sb2 = (const float*)d_in[4];
    const float* sW3 = (const float*)d_in[5];
    const float* sb3 = (const float*)d_in[6];
    const float* fW1 = (const float*)d_in[7];
    const float* fb1 = (const float*)d_in[8];
    const float* fW2 = (const float*)d_in[9];
    const float* fb2 = (const float*)d_in[10];
    float* out = (float*)d_out;

    float *h1, *f, *FL;
    __half *h2, *w3t, *S;
    cudaGetSymbolAddress((void**)&h1,  g_h1);
    cudaGetSymbolAddress((void**)&h2,  g_h2);
    cudaGetSymbolAddress((void**)&w3t, g_W3t);
    cudaGetSymbolAddress((void**)&S,   g_S);
    cudaGetSymbolAddress((void**)&f,   g_f);
    cudaGetSymbolAddress((void**)&FL,  g_FL);

    cudaFuncSetAttribute(gemm3_mma, cudaFuncAttributeMaxDynamicSharedMemorySize, 98304);

    dim3 blk(256);
    // spatial chain
    gemm64_act<0><<<dim3(4, 64), blk>>>(msg, sW1, sb1, h1, 4096, 256, 64);
    gemm64_relu_h16<<<dim3(8, 64), blk>>>(h1, sW2, sb2, h2, 4096, 512, 256);
    transpose_h16<<<dim3(4096 / 32, 512 / 32), dim3(32, 8)>>>(sW3, w3t, 512, 4096);
    gemm3_mma<<<dim3(32, 32), 256, 98304>>>(h2, w3t, sb3, S);
    // freq chain
    gemm64_act<0><<<dim3(2, 64), blk>>>(msg, fW1, fb1, f, 4096, 128, 64);
    gemm64_act<1><<<dim3(4, 64), blk>>>(f, fW2, fb2, FL, 4096, 256, 128);
    // assemble + depthwise Gaussian (one channel per CTA)
    assemble_conv<<<dim3(4096, 3), 256>>>(S, FL, msg, out);
}

// round 9
// speedup vs baseline: 1.6146x; 1.1422x over previous
#include <cuda_runtime.h>
#include <cuda_fp16.h>
#include <math.h>
#include <stdint.h>

// ---------------- scratch (static device globals; no allocation) ----------------
__device__ __half  g_msgh[4096 * 64];
__device__ __half  g_w1t [256 * 64];      // sW1^T fp16 [N,K]
__device__ __half  g_w2t [512 * 256];
__device__ __half  g_w3t [4096 * 512];
__device__ __half  g_fw1t[128 * 64];
__device__ __half  g_fw2t[256 * 128];
__device__ __half  g_h1  [4096 * 256];
__device__ __half  g_h2  [4096 * 512];
__device__ __half  g_S   [4096u * 4096u];
__device__ __half  g_f   [4096 * 128];
__device__ __half  g_FL  [4096 * 256];

// ---------------- helpers ----------------
__device__ __forceinline__ uint32_t smem_u32(const void* p) {
    uint32_t a;
    asm("{ .reg .u64 t; cvta.to.shared.u64 t, %1; cvt.u32.u64 %0, t; }" : "=r"(a) : "l"(p));
    return a;
}
__device__ __forceinline__ void cp_async16(uint32_t dst, const void* src) {
    asm volatile("cp.async.cg.shared.global [%0], [%1], 16;" :: "r"(dst), "l"(src));
}
#define CP_COMMIT() asm volatile("cp.async.commit_group;" ::: "memory")

__device__ __forceinline__ void ldsm_x4(uint32_t (&r)[4], uint32_t addr) {
    asm volatile("ldmatrix.sync.aligned.m8n8.x4.shared.b16 {%0,%1,%2,%3}, [%4];"
                 : "=r"(r[0]), "=r"(r[1]), "=r"(r[2]), "=r"(r[3]) : "r"(addr));
}
__device__ __forceinline__ void mma16816h(float (&d)[4], const uint32_t (&a)[4],
                                          uint32_t b0, uint32_t b1) {
    asm volatile(
        "mma.sync.aligned.m16n8k16.row.col.f32.f16.f16.f32 "
        "{%0,%1,%2,%3}, {%4,%5,%6,%7}, {%8,%9}, {%0,%1,%2,%3};"
        : "+f"(d[0]), "+f"(d[1]), "+f"(d[2]), "+f"(d[3])
        : "r"(a[0]), "r"(a[1]), "r"(a[2]), "r"(a[3]), "r"(b0), "r"(b1));
}

// ---------------- fp32 -> fp16 elementwise ----------------
__global__ __launch_bounds__(256) void f32_to_f16(
    const float* __restrict__ x, __half* __restrict__ y)
{
    int i = blockIdx.x * 256 + threadIdx.x;
    float2 v = reinterpret_cast<const float2*>(x)[i];
    reinterpret_cast<__half2*>(y)[i] = __floats2half2_rn(v.x, v.y);
}

// W [K,N] f32 -> W^T fp16 [N,K]
__global__ __launch_bounds__(256) void transpose_h16(
    const float* __restrict__ W, __half* __restrict__ T, int K, int N)
{
    __shared__ float t[32][33];
    int tx = threadIdx.x, ty = threadIdx.y;       // 32 x 8
    int bx = blockIdx.x, by = blockIdx.y;         // N/32, K/32
    #pragma unroll
    for (int i = 0; i < 4; i++) {
        int row = by * 32 + ty + i * 8;
        int col = bx * 32 + tx;
        t[ty + i * 8][tx] = W[(size_t)row * N + col];
    }
    __syncthreads();
    #pragma unroll
    for (int i = 0; i < 4; i++) {
        int n = bx * 32 + ty + i * 8;
        int k = by * 32 + tx;
        T[(size_t)n * K + k] = __float2half_rn(t[tx][ty + i * 8]);
    }
}

// ---------------- generic fp16 tensor GEMM: C = act(A @ Bt^T + bias) ----------------
// A [M,K] fp16 row-major, Bt [N,K] fp16 row-major, C [M,N] fp16.
// CTA 128x128, 8 warps (4m x 2n, warp 32x64). K in nch chunks of 64.
// Stage = 32 KB; 3-stage ring; order: wait_group -> barrier -> issue next load.
template <int ACT>  // 0 = relu, 1 = tanh
__global__ __launch_bounds__(256, 2) void gemmT_h16(
    const __half* __restrict__ A, const __half* __restrict__ Bt,
    const float* __restrict__ bias, __half* __restrict__ C,
    int K, int N, int nch)
{
    extern __shared__ char dynsmem[];
    const uint32_t sbase = smem_u32(dynsmem);

    const int tid  = threadIdx.x;
    const int lane = tid & 31;
    const int wid  = tid >> 5;
    const int wm   = wid & 3;
    const int wn   = wid >> 2;
    const int tile_n = blockIdx.x, tile_m = blockIdx.y;

    auto load_chunk = [&](int stage, int kc) {
        const uint32_t st = sbase + stage * 32768;
        #pragma unroll
        for (int it = 0; it < 8; it++) {
            int u   = tid + it * 256;
            int buf = u >> 10;                 // 0 = A, 1 = B
            int idx = u & 1023;
            int row = idx >> 3;
            int c   = idx & 7;
            uint32_t dst = st + buf * 16384 + row * 128 + ((c ^ (row & 7)) << 4);
            const __half* src = buf ? Bt : A;
            int grow = (buf ? tile_n : tile_m) * 128 + row;
            cp_async16(dst, (const char*)src + ((size_t)grow * K + kc * 64 + c * 8) * 2);
        }
        CP_COMMIT();
    };

    float acc[2][8][4];
    #pragma unroll
    for (int i = 0; i < 2; i++)
        #pragma unroll
        for (int j = 0; j < 8; j++)
            #pragma unroll
            for (int t = 0; t < 4; t++) acc[i][j][t] = 0.0f;

    load_chunk(0, 0);
    if (nch > 1) load_chunk(1, 1);

    const int a_row_in = (lane & 15);
    const int a_cb_add = (lane >> 4);
    const int b_row_in = ((lane >> 4) << 3) + (lane & 7);
    const int b_cb_add = (lane >> 3) & 1;

    for (int c = 0; c < nch; ++c) {
        if (c < nch - 1) asm volatile("cp.async.wait_group 1;" ::: "memory");
        else             asm volatile("cp.async.wait_group 0;" ::: "memory");
        __syncthreads();
        if (c + 2 < nch) load_chunk((c + 2) % 3, c + 2);

        const uint32_t aB = sbase + (c % 3) * 32768;
        const uint32_t bB = aB + 16384;

        #pragma unroll
        for (int kk = 0; kk < 4; kk++) {
            const int cb = kk * 2;
            uint32_t ah[2][4];
            #pragma unroll
            for (int mi = 0; mi < 2; mi++) {
                int row = wm * 32 + mi * 16 + a_row_in;
                uint32_t off = row * 128 + (((cb + a_cb_add) ^ (row & 7)) << 4);
                ldsm_x4(ah[mi], aB + off);
            }
            #pragma unroll
            for (int nq = 0; nq < 4; nq++) {
                int row = wn * 64 + nq * 16 + b_row_in;
                uint32_t off = row * 128 + (((cb + b_cb_add) ^ (row & 7)) << 4);
                uint32_t bh[4];
                ldsm_x4(bh, bB + off);
                #pragma unroll
                for (int mi = 0; mi < 2; mi++) {
                    mma16816h(acc[mi][2 * nq],     ah[mi], bh[0], bh[1]);
                    mma16816h(acc[mi][2 * nq + 1], ah[mi], bh[2], bh[3]);
                }
            }
        }
    }

    // epilogue: bias + act -> fp16
    const int col0 = tile_n * 128 + wn * 64 + (lane & 3) * 2;
    #pragma unroll
    for (int mi = 0; mi < 2; mi++) {
        int r0 = tile_m * 128 + wm * 32 + mi * 16 + (lane >> 2);
        #pragma unroll
        for (int nb = 0; nb < 8; nb++) {
            int col = col0 + nb * 8;
            float b0 = __ldg(bias + col), b1 = __ldg(bias + col + 1);
            float v0 = acc[mi][nb][0] + b0, v1 = acc[mi][nb][1] + b1;
            float v2 = acc[mi][nb][2] + b0, v3 = acc[mi][nb][3] + b1;
            if (ACT == 0) {
                v0 = fmaxf(v0, 0.f); v1 = fmaxf(v1, 0.f);
                v2 = fmaxf(v2, 0.f); v3 = fmaxf(v3, 0.f);
            } else {
                v0 = tanhf(v0); v1 = tanhf(v1);
                v2 = tanhf(v2); v3 = tanhf(v3);
            }
            *reinterpret_cast<__half2*>(C + (size_t)r0 * N + col) = __floats2half2_rn(v0, v1);
            *reinterpret_cast<__half2*>(C + (size_t)(r0 + 8) * N + col) = __floats2half2_rn(v2, v3);
        }
    }
}

// ---------------- assemble one channel + separable 5x5 Gaussian ----------------
__global__ __launch_bounds__(256) void assemble_conv(
    const __half* __restrict__ S, const __half* __restrict__ FL,
    const float* __restrict__ msg, float* __restrict__ out)
{
    __shared__ float img[64 * 64];
    __shared__ float tmp[64 * 64];
    __shared__ float fl[256];

    const int b   = blockIdx.x;
    const int ch  = blockIdx.y;
    const int tid = threadIdx.x;

    float g[5];
    {
        float s = 0.0f;
        #pragma unroll
        for (int i = 0; i < 5; i++) {
            float c = (float)(i - 2);
            g[i] = expf(-c * c * 0.5f);
            s += g[i];
        }
        #pragma unroll
        for (int i = 0; i < 5; i++) g[i] /= s;
    }

    if (ch == 0) {
        const __half2* S2 = reinterpret_cast<const __half2*>(S + (size_t)b * 4096);
        #pragma unroll
        for (int it = 0; it < 8; it++) {
            int i2 = tid + it * 256;
            float2 f = __half22float2(S2[i2]);
            img[2 * i2]     = f.x;
            img[2 * i2 + 1] = f.y;
        }
    } else if (ch == 1) {
        fl[tid] = __half2float(FL[(size_t)b * 256 + tid]);
        __syncthreads();
        #pragma unroll
        for (int it = 0; it < 16; it++) {
            int idx = tid + it * 256;
            int p = idx >> 6, q = idx & 63;
            float pp = (float)(p * 15) / 63.0f;
            float pq = (float)(q * 15) / 63.0f;
            int lp = (int)pp, lq = (int)pq;
            float wp = pp - (float)lp, wq = pq - (float)lq;
            int hp = min(lp + 1, 15), hq = min(lq + 1, 15);
            float v00 = fl[lp * 16 + lq], v01 = fl[lp * 16 + hq];
            float v10 = fl[hp * 16 + lq], v11 = fl[hp * 16 + hq];
            float top = (1.0f - wq) * v00 + wq * v01;
            float bot = (1.0f - wq) * v10 + wq * v11;
            img[idx] = (1.0f - wp) * top + wp * bot;
        }
    } else {
        if (tid < 64) fl[tid] = msg[(size_t)b * 64 + tid];
        __syncthreads();
        #pragma unroll
        for (int it = 0; it < 16; it++) {
            int idx = tid + it * 256;
            int p = idx >> 6, q = idx & 63;
            img[idx] = fl[((p >> 3) << 3) + (q >> 3)];
        }
    }
    __syncthreads();

    #pragma unroll
    for (int it = 0; it < 16; it++) {
        int idx = tid + it * 256;
        int p = idx >> 6, q = idx & 63;
        float s = 0.0f;
        #pragma unroll
        for (int d = -2; d <= 2; d++) {
            int qq = q + d;
            if (qq >= 0 && qq < 64) s = fmaf(g[d + 2], img[(p << 6) + qq], s);
        }
        tmp[idx] = s;
    }
    __syncthreads();

    float* outc = out + ((size_t)b * 3 + ch) * 4096;
    #pragma unroll
    for (int it = 0; it < 4; it++) {
        int i4 = tid + it * 256;
        int p  = i4 >> 4;
        int q0 = (i4 & 15) << 2;
        float4 s = make_float4(0.f, 0.f, 0.f, 0.f);
        #pragma unroll
        for (int d = -2; d <= 2; d++) {
            int pp = p + d;
            if (pp >= 0 && pp < 64) {
                float4 t4 = *reinterpret_cast<float4*>(&tmp[(pp << 6) + q0]);
                float w = g[d + 2];
                s.x = fmaf(w, t4.x, s.x);
                s.y = fmaf(w, t4.y, s.y);
                s.z = fmaf(w, t4.z, s.z);
                s.w = fmaf(w, t4.w, s.w);
            }
        }
        *reinterpret_cast<float4*>(outc + (p << 6) + q0) = s;
    }
}

// ---------------- launch ----------------
extern "C" void kernel_launch(void* const* d_in, const int* in_sizes, int n_in,
                              void* d_out, int out_size)
{
    const float* msg = (const float*)d_in[0];
    const float* sW1 = (const float*)d_in[1];
    const float* sb1 = (const float*)d_in[2];
    const float* sW2 = (const float*)d_in[3];
    const float* sb2 = (const float*)d_in[4];
    const float* sW3 = (const float*)d_in[5];
    const float* sb3 = (const float*)d_in[6];
    const float* fW1 = (const float*)d_in[7];
    const float* fb1 = (const float*)d_in[8];
    const float* fW2 = (const float*)d_in[9];
    const float* fb2 = (const float*)d_in[10];
    float* out = (float*)d_out;

    __half *msgh, *w1t, *w2t, *w3t, *fw1t, *fw2t, *h1, *h2, *S, *f, *FL;
    cudaGetSymbolAddress((void**)&msgh, g_msgh);
    cudaGetSymbolAddress((void**)&w1t,  g_w1t);
    cudaGetSymbolAddress((void**)&w2t,  g_w2t);
    cudaGetSymbolAddress((void**)&w3t,  g_w3t);
    cudaGetSymbolAddress((void**)&fw1t, g_fw1t);
    cudaGetSymbolAddress((void**)&fw2t, g_fw2t);
    cudaGetSymbolAddress((void**)&h1,   g_h1);
    cudaGetSymbolAddress((void**)&h2,   g_h2);
    cudaGetSymbolAddress((void**)&S,    g_S);
    cudaGetSymbolAddress((void**)&f,    g_f);
    cudaGetSymbolAddress((void**)&FL,   g_FL);

    cudaFuncSetAttribute(gemmT_h16<0>, cudaFuncAttributeMaxDynamicSharedMemorySize, 98304);
    cudaFuncSetAttribute(gemmT_h16<1>, cudaFuncAttributeMaxDynamicSharedMemorySize, 98304);

    // conversions / transposes
    f32_to_f16<<<4096 * 64 / 512, 256>>>(msg, msgh);
    transpose_h16<<<dim3(256 / 32, 64 / 32),   dim3(32, 8)>>>(sW1, w1t, 64, 256);
    transpose_h16<<<dim3(512 / 32, 256 / 32),  dim3(32, 8)>>>(sW2, w2t, 256, 512);
    transpose_h16<<<dim3(4096 / 32, 512 / 32), dim3(32, 8)>>>(sW3, w3t, 512, 4096);
    transpose_h16<<<dim3(128 / 32, 64 / 32),   dim3(32, 8)>>>(fW1, fw1t, 64, 128);
    transpose_h16<<<dim3(256 / 32, 128 / 32),  dim3(32, 8)>>>(fW2, fw2t, 128, 256);

    // spatial chain (all tensor)
    gemmT_h16<0><<<dim3(2, 32),  256, 98304>>>(msgh, w1t, sb1, h1, 64, 256, 1);
    gemmT_h16<0><<<dim3(4, 32),  256, 98304>>>(h1,   w2t, sb2, h2, 256, 512, 4);
    gemmT_h16<1><<<dim3(32, 32), 256, 98304>>>(h2,   w3t, sb3, S,  512, 4096, 8);
    // freq chain
    gemmT_h16<0><<<dim3(1, 32),  256, 98304>>>(msgh, fw1t, fb1, f,  64, 128, 1);
    gemmT_h16<1><<<dim3(2, 32),  256, 98304>>>(f,    fw2t, fb2, FL, 128, 256, 2);
    // assemble + depthwise Gaussian
    assemble_conv<<<dim3(4096, 3), 256>>>(S, FL, msg, out);
}